// round 9
// baseline (speedup 1.0000x reference)
#include <cuda_runtime.h>

// WorkingYOLOLoss on GB300 (sm_103a) — critical-path-minimized single launch.
// 100 blocks x 128 threads, one thread per target, 8 unpredicated clamped
// gathers (issue immediately after targets land), validity applied as a mask.
// pred:    d_in[0]  (64, 8, 256, 256) float32
// targets: d_in[1]  (64, 200, 5)      float32  [cls_id, x, y, w, h]
// out:     4 float32  [total, bbox_sum, obj_sum, cls_sum]

#define B_DIM 64
#define N_TGT 200
#define NTOT (B_DIM * N_TGT)     // 12800
#define HW 65536                 // 256*256
#define BBOX_W 0.05f
#define OBJ_W  1.0f
#define CLS_W  0.5f

#define THREADS 128
#define BLOCKS  (NTOT / THREADS) // 100

// Device scratch: accumulators + completion counter. Zeroed at load; the
// LAST block resets them after finalizing, so each graph replay starts clean.
__device__ float g_acc[3] = {0.f, 0.f, 0.f};
__device__ unsigned int g_done = 0;

__device__ __forceinline__ float softplus_f(float x) {
    return fmaxf(x, 0.0f) + log1pf(expf(-fabsf(x)));
}

__global__ void __launch_bounds__(THREADS) yolo_loss_kernel(
    const float* __restrict__ pred,
    const float* __restrict__ targets,
    float* __restrict__ out)
{
    int t = blockIdx.x * THREADS + threadIdx.x;   // always < NTOT (exact grid)

    const float* tr = targets + (size_t)t * 5;
    float cid = __ldg(tr + 0);
    float c0 = __ldg(tr + 1), c1 = __ldg(tr + 2);
    float c2 = __ldg(tr + 3), c3 = __ldg(tr + 4);

    // Address depends only on c0,c1 — compute + clamp immediately so the 8
    // gathers issue as soon as the targets load lands (no predicate stage).
    int xp = (int)(c0 * 256.0f);   // truncation, matches astype(int32)
    int yp = (int)(c1 * 256.0f);
    int xs = min(max(xp, 0), 255);
    int ys = min(max(yp, 0), 255);

    int b = t / N_TGT;             // compiler lowers to mul-shift
    const float* pp = pred + ((size_t)b << 19)     // b*8*HW
                           + ((size_t)ys << 8) + xs;

    // 8 independent unconditional channel loads — MLP=8
    float p0 = __ldg(pp + 0 * HW);
    float p1 = __ldg(pp + 1 * HW);
    float p2 = __ldg(pp + 2 * HW);
    float p3 = __ldg(pp + 3 * HW);
    float p4 = __ldg(pp + 4 * HW);
    float p5 = __ldg(pp + 5 * HW);
    float p6 = __ldg(pp + 6 * HW);
    float p7 = __ldg(pp + 7 * HW);

    // Validity mask (computed while loads are in flight)
    bool valid = (cid >= 0.0f) && ((c0 + c1 + c2 + c3) > 0.0f);
    bool inb = (xp >= 0) && (xp < 256) && (yp >= 0) && (yp < 256);
    float m = (valid && inb) ? 1.0f : 0.0f;

    float d0 = p0 - c0, d1 = p1 - c1, d2 = p2 - c2, d3 = p3 - c3;
    float bbox = m * 0.25f * (d0 * d0 + d1 * d1 + d2 * d2 + d3 * d3);

    float obj = m * (softplus_f(p4) - p4);          // BCE(z=1)

    int ci = (int)fmaxf(cid, 0.0f);                 // clip like the reference
    float s = softplus_f(p5) + softplus_f(p6) + softplus_f(p7);
    float pc = (ci == 0) ? p5 : ((ci == 1) ? p6 : p7);
    float cls = m * (s - pc) * (1.0f / 3.0f);

    // ---- warp reduce ----
    #pragma unroll
    for (int off = 16; off > 0; off >>= 1) {
        bbox += __shfl_down_sync(0xFFFFFFFFu, bbox, off);
        obj  += __shfl_down_sync(0xFFFFFFFFu, obj,  off);
        cls  += __shfl_down_sync(0xFFFFFFFFu, cls,  off);
    }

    // ---- block reduce across 4 warps ----
    __shared__ float s_red[3][4];
    int lane = threadIdx.x & 31;
    int wid  = threadIdx.x >> 5;
    if (lane == 0) {
        s_red[0][wid] = bbox;
        s_red[1][wid] = obj;
        s_red[2][wid] = cls;
    }
    __syncthreads();

    if (threadIdx.x == 0) {
        bbox = s_red[0][0] + s_red[0][1] + s_red[0][2] + s_red[0][3];
        obj  = s_red[1][0] + s_red[1][1] + s_red[1][2] + s_red[1][3];
        cls  = s_red[2][0] + s_red[2][1] + s_red[2][2] + s_red[2][3];

        atomicAdd(&g_acc[0], bbox);
        atomicAdd(&g_acc[1], obj);
        atomicAdd(&g_acc[2], cls);
        __threadfence();
        unsigned int ticket = atomicAdd(&g_done, 1u);
        if (ticket == (unsigned int)(gridDim.x - 1)) {
            // last block: finalize (single 128-bit store) + reset for next replay
            float fb = g_acc[0], fo = g_acc[1], fc = g_acc[2];
            float4 r;
            r.x = BBOX_W * fb + OBJ_W * fo + CLS_W * fc;
            r.y = fb;
            r.z = fo;
            r.w = fc;
            *(float4*)out = r;
            g_acc[0] = 0.0f;
            g_acc[1] = 0.0f;
            g_acc[2] = 0.0f;
            g_done = 0u;
            __threadfence();
        }
    }
}

extern "C" void kernel_launch(void* const* d_in, const int* in_sizes, int n_in,
                              void* d_out, int out_size) {
    const float* pred    = (const float*)d_in[0];
    const float* targets = (const float*)d_in[1];
    float* out = (float*)d_out;

    yolo_loss_kernel<<<BLOCKS, THREADS>>>(pred, targets, out);
}

// round 10
// speedup vs baseline: 1.0332x; 1.0332x over previous
#include <cuda_runtime.h>

// WorkingYOLOLoss on GB300 (sm_103a) — warp-granular tail, release/acquire
// ticket (no __syncthreads, no smem, no full threadfence on the exit path).
// 100 blocks x 128 threads, one thread per target, 8 unpredicated gathers.
// pred:    d_in[0]  (64, 8, 256, 256) float32
// targets: d_in[1]  (64, 200, 5)      float32  [cls_id, x, y, w, h]
// out:     4 float32  [total, bbox_sum, obj_sum, cls_sum]

#define B_DIM 64
#define N_TGT 200
#define NTOT (B_DIM * N_TGT)     // 12800
#define HW 65536                 // 256*256
#define BBOX_W 0.05f
#define OBJ_W  1.0f
#define CLS_W  0.5f

#define THREADS 128
#define BLOCKS  (NTOT / THREADS) // 100
#define NWARPS  (BLOCKS * THREADS / 32)  // 400 warp-level arrivals

// Device scratch: accumulators + completion counter. Zeroed at load; the
// LAST warp resets them after finalizing, so each graph replay starts clean.
__device__ float g_acc[3] = {0.f, 0.f, 0.f};
__device__ unsigned int g_done = 0;

__device__ __forceinline__ float softplus_f(float x) {
    return fmaxf(x, 0.0f) + log1pf(expf(-fabsf(x)));
}

__device__ __forceinline__ unsigned int ticket_release(unsigned int* p) {
    unsigned int old;
    asm volatile("atom.add.release.gpu.u32 %0, [%1], 1;"
                 : "=r"(old) : "l"(p) : "memory");
    return old;
}

__device__ __forceinline__ float ld_acquire(const float* p) {
    float v;
    asm volatile("ld.acquire.gpu.f32 %0, [%1];" : "=f"(v) : "l"(p) : "memory");
    return v;
}

__global__ void __launch_bounds__(THREADS) yolo_loss_kernel(
    const float* __restrict__ pred,
    const float* __restrict__ targets,
    float* __restrict__ out)
{
    int t = blockIdx.x * THREADS + threadIdx.x;   // always < NTOT (exact grid)

    const float* tr = targets + (size_t)t * 5;
    float cid = __ldg(tr + 0);
    float c0 = __ldg(tr + 1), c1 = __ldg(tr + 2);
    float c2 = __ldg(tr + 3), c3 = __ldg(tr + 4);

    // Address depends only on c0,c1 — clamp + issue gathers immediately.
    int xp = (int)(c0 * 256.0f);   // truncation, matches astype(int32)
    int yp = (int)(c1 * 256.0f);
    int xs = min(max(xp, 0), 255);
    int ys = min(max(yp, 0), 255);

    int b = t / N_TGT;
    const float* pp = pred + ((size_t)b << 19)     // b*8*HW
                           + ((size_t)ys << 8) + xs;

    // 8 independent unconditional channel loads — MLP=8
    float p0 = __ldg(pp + 0 * HW);
    float p1 = __ldg(pp + 1 * HW);
    float p2 = __ldg(pp + 2 * HW);
    float p3 = __ldg(pp + 3 * HW);
    float p4 = __ldg(pp + 4 * HW);
    float p5 = __ldg(pp + 5 * HW);
    float p6 = __ldg(pp + 6 * HW);
    float p7 = __ldg(pp + 7 * HW);

    // Validity mask (computed while loads are in flight)
    bool valid = (cid >= 0.0f) && ((c0 + c1 + c2 + c3) > 0.0f);
    bool inb = (xp >= 0) && (xp < 256) && (yp >= 0) && (yp < 256);
    float m = (valid && inb) ? 1.0f : 0.0f;

    float d0 = p0 - c0, d1 = p1 - c1, d2 = p2 - c2, d3 = p3 - c3;
    float bbox = m * 0.25f * (d0 * d0 + d1 * d1 + d2 * d2 + d3 * d3);

    float obj = m * (softplus_f(p4) - p4);          // BCE(z=1)

    int ci = (int)fmaxf(cid, 0.0f);
    float s = softplus_f(p5) + softplus_f(p6) + softplus_f(p7);
    float pc = (ci == 0) ? p5 : ((ci == 1) ? p6 : p7);
    float cls = m * (s - pc) * (1.0f / 3.0f);

    // ---- warp reduce ----
    #pragma unroll
    for (int off = 16; off > 0; off >>= 1) {
        bbox += __shfl_down_sync(0xFFFFFFFFu, bbox, off);
        obj  += __shfl_down_sync(0xFFFFFFFFu, obj,  off);
        cls  += __shfl_down_sync(0xFFFFFFFFu, cls,  off);
    }

    // ---- warp-granular global accumulate + release ticket ----
    if ((threadIdx.x & 31) == 0) {
        atomicAdd(&g_acc[0], bbox);   // result unused -> RED
        atomicAdd(&g_acc[1], obj);
        atomicAdd(&g_acc[2], cls);
        unsigned int ticket = ticket_release(&g_done);
        if (ticket == (unsigned int)(NWARPS - 1)) {
            // last warp: acquire-read totals, finalize, reset for next replay
            float fb = ld_acquire(&g_acc[0]);
            float fo = ld_acquire(&g_acc[1]);
            float fc = ld_acquire(&g_acc[2]);
            float4 r;
            r.x = BBOX_W * fb + OBJ_W * fo + CLS_W * fc;
            r.y = fb;
            r.z = fo;
            r.w = fc;
            *(float4*)out = r;
            g_acc[0] = 0.0f;
            g_acc[1] = 0.0f;
            g_acc[2] = 0.0f;
            g_done = 0u;
        }
    }
}

extern "C" void kernel_launch(void* const* d_in, const int* in_sizes, int n_in,
                              void* d_out, int out_size) {
    const float* pred    = (const float*)d_in[0];
    const float* targets = (const float*)d_in[1];
    float* out = (float*)d_out;

    yolo_loss_kernel<<<BLOCKS, THREADS>>>(pred, targets, out);
}